// round 8
// baseline (speedup 1.0000x reference)
#include <cuda_runtime.h>
#include <cuda_bf16.h>
#include <cstdint>

#define LV       4087
#define BROWS    2048
#define NSTEP    1021
#define NCH      4096
#define EPSF     1e-6f
#define CSTRIDE  4096
#define PADSTEP  1032
#define NROWS    1023            // atoms 1..1023 stored
#define NPAIR    (NROWS * BROWS)

// [step][chain] coefficients: {-l*ct, l*st*cos(chi), l*st*sin(chi), 0}  (67.6MB)
__device__ float4 g_coef[(size_t)PADSTEP * NCH];
// [atom-1][chain] positions, atoms 1..1023 (67MB)
__device__ float4 g_pos[(size_t)NROWS * NCH];
__device__ float4 g_init[NCH];   // {l1, -l2*ct0, l2*st0, 0}
__device__ double g_acc;
__device__ unsigned g_count;

__device__ __forceinline__ float dnbl(float v) { return ((v + 1.0f) * 0.5f) * 2.1f + 0.9f; }
__device__ __forceinline__ float dnd (float v) { return ((v + 1.0f) * 0.5f) * 3.5f + 1.5f; }
__device__ __forceinline__ float clip1(float v) { return fminf(fmaxf(v, -1.0f), 1.0f); }

__device__ __forceinline__ float rsq_approx(float x) {
    float y; asm("rsqrt.approx.f32 %0, %1;" : "=f"(y) : "f"(x)); return y;
}

// ---------------------------------------------------------------------------
// Prep: lane = step (coalesced reads), smem transpose, coalesced writes.
// Folds per-chain init + accumulator reset.  (measured 42.7us, issue-bound)
// ---------------------------------------------------------------------------
__global__ __launch_bounds__(1024) void prep_kernel(const float* __restrict__ pred,
                                                    const float* __restrict__ targ)
{
    __shared__ float4 T[32][33];
    const int tx = threadIdx.x;
    const int ty = threadIdx.y;
    const int J0 = blockIdx.x * 32;
    const int C0 = blockIdx.y * 32;
    const int c  = C0 + ty;
    const int j  = J0 + tx;
    const int row = c & (BROWS - 1);
    const bool isP = c < BROWS;
    const float* __restrict__ v = (isP ? pred : targ) + (size_t)row * LV;

    if (blockIdx.x == 0 && blockIdx.y == 0 && tx == 0 && ty == 0) {
        g_acc = 0.0;
        g_count = 0u;
    }

    if (blockIdx.x == 0 && tx == 0) {
        float b0 = v[3064], b1 = v[3065], dr = v[2042];
        if (isP) { b0 = clip1(b0); b1 = clip1(b1); dr = clip1(dr); }
        float l1 = dnbl(b0), l2 = dnbl(b1), dd = dnd(dr);
        float ct = (l1 * l1 + l2 * l2 - dd * dd) / (2.0f * l1 * l2);
        ct = fminf(fmaxf(ct, -1.0f + EPSF), 1.0f - EPSF);
        float st = sqrtf((1.0f - ct) * (1.0f + ct));
        g_init[c] = make_float4(l1, -l2 * ct, l2 * st, 0.0f);
    }

    float4 o = make_float4(0.f, 0.f, 0.f, 0.f);
    if (j < NSTEP) {
        float b1r = v[3064 + j + 1];
        float b2r = v[3064 + j + 2];
        float dr  = v[2042 + j + 1];
        float s0  = v[2 * j];
        float s1  = v[2 * j + 1];
        if (isP) {
            b1r = clip1(b1r); b2r = clip1(b2r); dr = clip1(dr);
            s0 = clip1(s0);   s1 = clip1(s1);
        }
        float l1 = dnbl(b1r), l = dnbl(b2r), dd = dnd(dr);
        float ct = (l1 * l1 + l * l - dd * dd) / (2.0f * l1 * l);
        ct = fminf(fmaxf(ct, -1.0f + EPSF), 1.0f - EPSF);
        float st = sqrtf((1.0f - ct) * (1.0f + ct));

        float h2 = s0 * s0 + s1 * s1;
        float cch, sch;
        if (h2 < 1e-30f) { cch = 1.0f; sch = 0.0f; }
        else { float rh = rsqrtf(h2); cch = s1 * rh; sch = s0 * rh; }

        o.x = -l * ct;
        o.y =  l * st * cch;
        o.z =  l * st * sch;
    }
    T[ty][tx] = o;
    __syncthreads();

    int jo = J0 + ty;
    if (jo < 1024)
        g_coef[(size_t)jo * CSTRIDE + (C0 + tx)] = T[tx][ty];
}

// ---------------------------------------------------------------------------
// Scan step (R7 math, measured-best): in-step true norms, self-correcting.
//   c12 = u1 x u2 ; cxu = c12 x u2 ; A2=|u2|^2 ; C2=|c12|^2
//   inv1 ~ 1/(|u2|+eps) ; rcpD ~ 1/(|c12|+eps*|u2|)   (2 MUFU + folds)
//   e = s1*u2 + s2*cxu + s3*c12 ; position streamed out via STG.128.
// ---------------------------------------------------------------------------
__device__ __forceinline__ void step_fn(const float4 cf,
    float& u1x, float& u1y, float& u1z,
    float& u2x, float& u2y, float& u2z,
    float& cx, float& cy, float& cz,
    float4* __restrict__ outp)
{
    float c12x = fmaf(u1y, u2z, -u1z * u2y);
    float c12y = fmaf(u1z, u2x, -u1x * u2z);
    float c12z = fmaf(u1x, u2y, -u1y * u2x);

    float cxux = fmaf(c12y, u2z, -c12z * u2y);
    float cxuy = fmaf(c12z, u2x, -c12x * u2z);
    float cxuz = fmaf(c12x, u2y, -c12y * u2x);

    float A2 = fmaf(u2x, u2x, fmaf(u2y, u2y, u2z * u2z));
    float C2 = fmaf(c12x, c12x, fmaf(c12y, c12y, c12z * c12z));

    float r1   = rsq_approx(A2);
    float inv1 = fmaf(-EPSF * r1, r1, r1);      // 1/(|u2|+eps)
    float an   = A2 * r1;                       // |u2|
    float rC   = rsq_approx(C2);                // 1/|c12|
    float t    = an * rC;
    float rcpD = fmaf(-EPSF * t, rC, rC);       // 1/(|c12|+eps*|u2|)

    float s1 = cf.x * inv1;
    float s3 = cf.z * rcpD;
    float s2 = (cf.y * inv1) * rcpD;

    float ex = fmaf(s1, u2x, fmaf(s2, cxux, s3 * c12x));
    float ey = fmaf(s1, u2y, fmaf(s2, cxuy, s3 * c12y));
    float ez = fmaf(s1, u2z, fmaf(s2, cxuz, s3 * c12z));

    float dx = cx + ex, dy = cy + ey, dz = cz + ez;
    u1x = u2x; u1y = u2y; u1z = u2z;
    u2x = ex;  u2y = ey;  u2z = ez;
    cx = dx;   cy = dy;   cz = dz;

    *outp = make_float4(dx, dy, dz, 0.0f);
}

// 512 threads/block, 8 blocks: 16 warps/SM on 8 SMs -> 4 warps per SMSP.
// Stall cycles of one warp are filled by the other three; scan goes from
// latency-bound (~400 cyc/step) to issue-bound (~I cyc/step).
__global__ void __launch_bounds__(512) scan_kernel()
{
    int chain = blockIdx.x * 512 + threadIdx.x;

    float4 ini = g_init[chain];
    float u1x = ini.x, u1y = 0.f, u1z = 0.f;       // a1-a0
    float u2x = ini.y, u2y = ini.z, u2z = 0.f;     // a2-a1
    float cx = ini.x + ini.y, cy = ini.z, cz = 0.f;

    float4* op = g_pos + chain;
    op[0]                 = make_float4(ini.x, 0.f, 0.f, 0.f);  // atom 1
    op[(size_t)CSTRIDE]   = make_float4(cx, cy, 0.f, 0.f);      // atom 2
    op += (size_t)2 * CSTRIDE;                                  // atom 3 row

    const float4* p = g_coef + chain;
    float4 b0 = __ldg(p);
    float4 b1 = __ldg(p + (size_t)CSTRIDE);

#pragma unroll 1
    for (int g = 0; g < 510; ++g) {          // rows 0..1019
        const float4* pn = p + (size_t)2 * CSTRIDE;
        float4 c0 = b0, c1 = b1;
        b0 = __ldg(pn);
        b1 = __ldg(pn + (size_t)CSTRIDE);
        step_fn(c0, u1x, u1y, u1z, u2x, u2y, u2z, cx, cy, cz, op);
        op += (size_t)CSTRIDE;
        step_fn(c1, u1x, u1y, u1z, u2x, u2y, u2z, cx, cy, cz, op);
        op += (size_t)CSTRIDE;
        p = pn;
    }
    // rows 1020 (in b0); row 1021 prefetched harmlessly within pad
    step_fn(b0, u1x, u1y, u1z, u2x, u2y, u2z, cx, cy, cz, op);
}

// ---------------------------------------------------------------------------
// Reduce: sum |pred - targ|^2 over [1023][2048] float4 pairs; last block
// writes the mean. 67MB coalesced reads.
// ---------------------------------------------------------------------------
__global__ __launch_bounds__(256) void reduce_kernel(float* __restrict__ out)
{
    __shared__ double sh[256];
    int tid = threadIdx.x;
    float acc = 0.f;
    for (size_t i = (size_t)blockIdx.x * 256 + tid; i < (size_t)NPAIR;
         i += (size_t)gridDim.x * 256) {
        size_t r = i >> 11;
        size_t c = i & 2047;
        float4 pv = g_pos[r * CSTRIDE + c];
        float4 tv = g_pos[r * CSTRIDE + c + BROWS];
        float fx = pv.x - tv.x, fy = pv.y - tv.y, fz = pv.z - tv.z;
        acc = fmaf(fx, fx, acc);
        acc = fmaf(fy, fy, acc);
        acc = fmaf(fz, fz, acc);
    }
    sh[tid] = (double)acc;
    __syncthreads();
#pragma unroll
    for (int s = 128; s > 0; s >>= 1) {
        if (tid < s) sh[tid] += sh[tid + s];
        __syncthreads();
    }
    if (tid == 0) {
        atomicAdd(&g_acc, sh[0]);
        __threadfence();
        unsigned old = atomicAdd(&g_count, 1u);
        if (old == (unsigned)(gridDim.x - 1)) {
            double total;
            asm volatile("ld.global.cg.f64 %0, [%1];" : "=d"(total) : "l"(&g_acc));
            out[0] = (float)(total * (1.0 / (2048.0 * 1024.0 * 3.0)));
        }
    }
}

extern "C" void kernel_launch(void* const* d_in, const int* in_sizes, int n_in,
                              void* d_out, int out_size)
{
    const float* pred = (const float*)d_in[0];
    const float* targ = (const float*)d_in[1];
    float* out = (float*)d_out;

    dim3 pb(32, 32), pg(32, NCH / 32);
    prep_kernel<<<pg, pb>>>(pred, targ);
    scan_kernel<<<NCH / 512, 512>>>();
    reduce_kernel<<<1024, 256>>>(out);
}

// round 9
// speedup vs baseline: 1.3387x; 1.3387x over previous
#include <cuda_runtime.h>
#include <cuda_bf16.h>
#include <cstdint>

#define LV       4087
#define BROWS    2048
#define NSTEP    1021
#define NCH      4096
#define EPSF     1e-6f
#define CSTRIDE  4096
#define PADSTEP  1032

// [step][chain] coefficients: {-l*ct, l*st*cos(chi), l*st*sin(chi), 0}  (67.6MB)
__device__ float4 g_coef[(size_t)PADSTEP * NCH];
__device__ float4 g_init[NCH];   // {l1, -l2*ct0, l2*st0, 0}
__device__ double g_acc;
__device__ unsigned g_count;

__device__ __forceinline__ float dnbl(float v) { return ((v + 1.0f) * 0.5f) * 2.1f + 0.9f; }
__device__ __forceinline__ float dnd (float v) { return ((v + 1.0f) * 0.5f) * 3.5f + 1.5f; }
__device__ __forceinline__ float clip1(float v) { return fminf(fmaxf(v, -1.0f), 1.0f); }

__device__ __forceinline__ float rsq_approx(float x) {
    float y; asm("rsqrt.approx.f32 %0, %1;" : "=f"(y) : "f"(x)); return y;
}

// ---------------------------------------------------------------------------
// Prep: lane = step (coalesced reads), smem transpose, coalesced writes.
// Folds per-chain init + accumulator reset.
// ---------------------------------------------------------------------------
__global__ __launch_bounds__(1024) void prep_kernel(const float* __restrict__ pred,
                                                    const float* __restrict__ targ)
{
    __shared__ float4 T[32][33];
    const int tx = threadIdx.x;
    const int ty = threadIdx.y;
    const int J0 = blockIdx.x * 32;
    const int C0 = blockIdx.y * 32;
    const int c  = C0 + ty;
    const int j  = J0 + tx;
    const int row = c & (BROWS - 1);
    const bool isP = c < BROWS;
    const float* __restrict__ v = (isP ? pred : targ) + (size_t)row * LV;

    if (blockIdx.x == 0 && blockIdx.y == 0 && tx == 0 && ty == 0) {
        g_acc = 0.0;
        g_count = 0u;
    }

    if (blockIdx.x == 0 && tx == 0) {
        float b0 = v[3064], b1 = v[3065], dr = v[2042];
        if (isP) { b0 = clip1(b0); b1 = clip1(b1); dr = clip1(dr); }
        float l1 = dnbl(b0), l2 = dnbl(b1), dd = dnd(dr);
        float ct = (l1 * l1 + l2 * l2 - dd * dd) / (2.0f * l1 * l2);
        ct = fminf(fmaxf(ct, -1.0f + EPSF), 1.0f - EPSF);
        float st = sqrtf((1.0f - ct) * (1.0f + ct));
        g_init[c] = make_float4(l1, -l2 * ct, l2 * st, 0.0f);
    }

    float4 o = make_float4(0.f, 0.f, 0.f, 0.f);
    if (j < NSTEP) {
        float b1r = v[3064 + j + 1];
        float b2r = v[3064 + j + 2];
        float dr  = v[2042 + j + 1];
        float s0  = v[2 * j];
        float s1  = v[2 * j + 1];
        if (isP) {
            b1r = clip1(b1r); b2r = clip1(b2r); dr = clip1(dr);
            s0 = clip1(s0);   s1 = clip1(s1);
        }
        float l1 = dnbl(b1r), l = dnbl(b2r), dd = dnd(dr);
        float ct = (l1 * l1 + l * l - dd * dd) / (2.0f * l1 * l);
        ct = fminf(fmaxf(ct, -1.0f + EPSF), 1.0f - EPSF);
        float st = sqrtf((1.0f - ct) * (1.0f + ct));

        float h2 = s0 * s0 + s1 * s1;
        float cch, sch;
        if (h2 < 1e-30f) { cch = 1.0f; sch = 0.0f; }
        else { float rh = rsqrtf(h2); cch = s1 * rh; sch = s0 * rh; }

        o.x = -l * ct;
        o.y =  l * st * cch;
        o.z =  l * st * sch;
    }
    T[ty][tx] = o;
    __syncthreads();

    int jo = J0 + ty;
    if (jo < 1024)
        g_coef[(size_t)jo * CSTRIDE + (C0 + tx)] = T[tx][ty];
}

// ---------------------------------------------------------------------------
// One scan step (R7 math, measured-best numerics). Returns new bond e via refs.
// ---------------------------------------------------------------------------
__device__ __forceinline__ void step_one(const float4 cf,
    float& u1x, float& u1y, float& u1z,
    float& u2x, float& u2y, float& u2z,
    float& ex, float& ey, float& ez)
{
    float c12x = fmaf(u1y, u2z, -u1z * u2y);
    float c12y = fmaf(u1z, u2x, -u1x * u2z);
    float c12z = fmaf(u1x, u2y, -u1y * u2x);

    float cxux = fmaf(c12y, u2z, -c12z * u2y);
    float cxuy = fmaf(c12z, u2x, -c12x * u2z);
    float cxuz = fmaf(c12x, u2y, -c12y * u2x);

    float A2 = fmaf(u2x, u2x, fmaf(u2y, u2y, u2z * u2z));
    float C2 = fmaf(c12x, c12x, fmaf(c12y, c12y, c12z * c12z));

    float r1   = rsq_approx(A2);
    float inv1 = fmaf(-EPSF * r1, r1, r1);      // 1/(|u2|+eps)
    float an   = A2 * r1;                       // |u2|
    float rC   = rsq_approx(C2);                // 1/|c12|
    float t    = an * rC;
    float rcpD = fmaf(-EPSF * t, rC, rC);       // 1/(|c12|+eps*|u2|)

    float s1 = cf.x * inv1;
    float s3 = cf.z * rcpD;
    float s2 = (cf.y * inv1) * rcpD;

    ex = fmaf(s1, u2x, fmaf(s2, cxux, s3 * c12x));
    ey = fmaf(s1, u2y, fmaf(s2, cxuy, s3 * c12y));
    ez = fmaf(s1, u2z, fmaf(s2, cxuz, s3 * c12z));

    u1x = u2x; u1y = u2y; u1z = u2z;
    u2x = ex;  u2y = ey;  u2z = ez;
}

// ---------------------------------------------------------------------------
// Scan: one thread = one row = pred chain + targ chain (ILP-2). Loss tracked
// in-register via position difference D; no shfl, no position storage.
// 64 blocks x 32 threads spread over 64 SMs (per-SM traffic stays tiny).
// ---------------------------------------------------------------------------
__global__ void __launch_bounds__(32) scan_kernel(float* __restrict__ out)
{
    int row = blockIdx.x * 32 + threadIdx.x;     // 0..2047

    float4 iP = g_init[row];
    float4 iT = g_init[row + BROWS];

    // pred chain state
    float Pu1x = iP.x, Pu1y = 0.f, Pu1z = 0.f;
    float Pu2x = iP.y, Pu2y = iP.z, Pu2z = 0.f;
    // targ chain state
    float Tu1x = iT.x, Tu1y = 0.f, Tu1z = 0.f;
    float Tu2x = iT.y, Tu2y = iT.z, Tu2z = 0.f;

    // position difference D = pos_pred - pos_targ (atom 2 onward updated)
    float Dx = (iP.x + iP.y) - (iT.x + iT.y);
    float Dy = iP.z - iT.z;
    float Dz = 0.f;

    float accx = 0.f, accy = 0.f, accz = 0.f;
    {   // atom 1 diff = (l1P - l1T, 0, 0); atom 2 diff = current D
        float d1 = iP.x - iT.x;
        accx = fmaf(d1, d1, accx);
        accx = fmaf(Dx, Dx, accx);
        accy = fmaf(Dy, Dy, accy);
    }

    const float4* pP = g_coef + row;
    const float4* pT = g_coef + row + BROWS;
    float4 bP[4], bT[4];
#pragma unroll
    for (int u = 0; u < 4; ++u) {
        bP[u] = __ldg(pP + (size_t)u * CSTRIDE);
        bT[u] = __ldg(pT + (size_t)u * CSTRIDE);
    }

#pragma unroll 1
    for (int g = 0; g < 254; ++g) {              // rows 0..1015
        const float4* nP = pP + (size_t)4 * CSTRIDE;
        const float4* nT = pT + (size_t)4 * CSTRIDE;
#pragma unroll
        for (int u = 0; u < 4; ++u) {
            float4 cP = bP[u], cT = bT[u];
            bP[u] = __ldg(nP + (size_t)u * CSTRIDE);
            bT[u] = __ldg(nT + (size_t)u * CSTRIDE);
            float ePx, ePy, ePz, eTx, eTy, eTz;
            step_one(cP, Pu1x, Pu1y, Pu1z, Pu2x, Pu2y, Pu2z, ePx, ePy, ePz);
            step_one(cT, Tu1x, Tu1y, Tu1z, Tu2x, Tu2y, Tu2z, eTx, eTy, eTz);
            Dx += ePx - eTx; Dy += ePy - eTy; Dz += ePz - eTz;
            accx = fmaf(Dx, Dx, accx);
            accy = fmaf(Dy, Dy, accy);
            accz = fmaf(Dz, Dz, accz);
        }
        pP = nP; pT = nT;
    }
#pragma unroll
    for (int u = 0; u < 4; ++u) {                // rows 1016..1019
        float ePx, ePy, ePz, eTx, eTy, eTz;
        step_one(bP[u], Pu1x, Pu1y, Pu1z, Pu2x, Pu2y, Pu2z, ePx, ePy, ePz);
        step_one(bT[u], Tu1x, Tu1y, Tu1z, Tu2x, Tu2y, Tu2z, eTx, eTy, eTz);
        Dx += ePx - eTx; Dy += ePy - eTy; Dz += ePz - eTz;
        accx = fmaf(Dx, Dx, accx);
        accy = fmaf(Dy, Dy, accy);
        accz = fmaf(Dz, Dz, accz);
    }
    {   // row 1020
        float4 cP = __ldg(pP + (size_t)4 * CSTRIDE);
        float4 cT = __ldg(pT + (size_t)4 * CSTRIDE);
        float ePx, ePy, ePz, eTx, eTy, eTz;
        step_one(cP, Pu1x, Pu1y, Pu1z, Pu2x, Pu2y, Pu2z, ePx, ePy, ePz);
        step_one(cT, Tu1x, Tu1y, Tu1z, Tu2x, Tu2y, Tu2z, eTx, eTy, eTz);
        Dx += ePx - eTx; Dy += ePy - eTy; Dz += ePz - eTz;
        accx = fmaf(Dx, Dx, accx);
        accy = fmaf(Dy, Dy, accy);
        accz = fmaf(Dz, Dz, accz);
    }

    float acc = accx + accy + accz;
#pragma unroll
    for (int off = 16; off > 0; off >>= 1)
        acc += __shfl_xor_sync(0xffffffffu, acc, off);

    if (threadIdx.x == 0) {
        atomicAdd(&g_acc, (double)acc);
        __threadfence();
        unsigned old = atomicAdd(&g_count, 1u);
        if (old == (unsigned)(gridDim.x - 1)) {
            double total;
            asm volatile("ld.global.cg.f64 %0, [%1];" : "=d"(total) : "l"(&g_acc));
            out[0] = (float)(total * (1.0 / (2048.0 * 1024.0 * 3.0)));
        }
    }
}

extern "C" void kernel_launch(void* const* d_in, const int* in_sizes, int n_in,
                              void* d_out, int out_size)
{
    const float* pred = (const float*)d_in[0];
    const float* targ = (const float*)d_in[1];
    float* out = (float*)d_out;

    dim3 pb(32, 32), pg(32, NCH / 32);
    prep_kernel<<<pg, pb>>>(pred, targ);
    scan_kernel<<<BROWS / 32, 32>>>(out);
}